// round 1
// baseline (speedup 1.0000x reference)
#include <cuda_runtime.h>
#include <math.h>

// Problem constants
#define BB 32
#define HW 12544          // 112*112
#define CC 128
#define RR 2048
#define CHUNKS 56
#define POS_PER_BLOCK (HW / CHUNKS)   // 224
#define N4_TOTAL (BB * HW * (CC/4))   // 12,845,056 float4s

// Scratch (device globals: no allocation allowed)
__device__ float g_partial[BB * CHUNKS * CC];
__device__ float g_gate[BB * CC];

// ---------------------------------------------------------------------------
// Kernel 1: partial global-average-pool. Each block sums POS_PER_BLOCK spatial
// positions for one (batch, chunk) over all 128 channels. Fully coalesced
// float4 reads; smem reduce; one float4 store per channel-quad.
// ---------------------------------------------------------------------------
__global__ void __launch_bounds__(256) pool_kernel(const float* __restrict__ x) {
    const int blk   = blockIdx.x;           // 0 .. B*CHUNKS-1
    const int b     = blk / CHUNKS;
    const int chunk = blk % CHUNKS;
    const int t     = threadIdx.x;          // 256
    const int lane  = t & 31;               // channel quad (c/4)
    const int grp   = t >> 5;               // 0..7 position offset

    const float4* xb = (const float4*)x
        + (size_t)b * HW * (CC/4)
        + (size_t)chunk * POS_PER_BLOCK * (CC/4);

    float4 acc = make_float4(0.f, 0.f, 0.f, 0.f);
    #pragma unroll 4
    for (int p = grp; p < POS_PER_BLOCK; p += 8) {
        float4 v = xb[(size_t)p * (CC/4) + lane];
        acc.x += v.x; acc.y += v.y; acc.z += v.z; acc.w += v.w;
    }

    __shared__ float4 sm[256];
    sm[t] = acc;
    __syncthreads();

    if (t < 32) {
        float4 s = sm[t];
        #pragma unroll
        for (int j = 1; j < 8; j++) {
            float4 v = sm[t + 32 * j];
            s.x += v.x; s.y += v.y; s.z += v.z; s.w += v.w;
        }
        ((float4*)g_partial)[(size_t)blk * 32 + t] = s;
    }
}

// ---------------------------------------------------------------------------
// Kernel 2: excite. One block per batch. Reduce partials -> mean s[128],
// h = gelu(s@w1 + b1) into smem, g = sigmoid(h@w2 + b2) -> g_gate.
// ---------------------------------------------------------------------------
__global__ void __launch_bounds__(256) excite_kernel(
    const float* __restrict__ w1, const float* __restrict__ b1,
    const float* __restrict__ w2, const float* __restrict__ b2)
{
    const int b = blockIdx.x;
    const int t = threadIdx.x;

    __shared__ float s[CC];
    __shared__ float h[RR];
    __shared__ float red[256];

    // reduce CHUNKS partials per channel -> mean
    if (t < CC) {
        float sum = 0.f;
        const float* p = g_partial + (size_t)b * CHUNKS * CC + t;
        #pragma unroll
        for (int k = 0; k < CHUNKS; k++) sum += p[(size_t)k * CC];
        s[t] = sum * (1.0f / (float)HW);
    }
    __syncthreads();

    // h[r] = gelu_tanh( sum_c s[c]*w1[c][r] + b1[r] ), 8 r per thread
    #pragma unroll
    for (int rr = 0; rr < RR / 256; rr++) {
        const int r = rr * 256 + t;
        float acc = b1[r];
        #pragma unroll 8
        for (int c = 0; c < CC; c++)
            acc = fmaf(s[c], w1[(size_t)c * RR + r], acc);
        // tanh-approx GELU (jax.nn.gelu default)
        const float u = acc;
        const float inner = 0.7978845608028654f * (u + 0.044715f * u * u * u);
        h[r] = 0.5f * u * (1.0f + tanhf(inner));
    }
    __syncthreads();

    // g[c] = sigmoid( sum_r h[r]*w2[r][c] + b2[c] ), 2 threads per channel
    const int c    = t & 127;
    const int half = t >> 7;     // 0 or 1
    float acc = 0.f;
    const float* w2p = w2 + (size_t)half * (RR / 2) * CC + c;
    const float* hp  = h + half * (RR / 2);
    #pragma unroll 8
    for (int r = 0; r < RR / 2; r++)
        acc = fmaf(hp[r], w2p[(size_t)r * CC], acc);
    red[t] = acc;
    __syncthreads();

    if (t < CC) {
        const float v = red[t] + red[t + 128] + b2[t];
        g_gate[b * CC + t] = 1.0f / (1.0f + expf(-v));
    }
}

// ---------------------------------------------------------------------------
// Kernel 3: out = x * gate[b, c]  (float4 vectorized, gate hits L1/L2)
// ---------------------------------------------------------------------------
__global__ void __launch_bounds__(256) scale_kernel(const float* __restrict__ x,
                                                    float* __restrict__ out) {
    const unsigned idx = blockIdx.x * 256u + threadIdx.x;   // float4 index
    if (idx >= (unsigned)N4_TOTAL) return;
    const unsigned b  = idx / (HW * (CC / 4));   // / 401408
    const unsigned c4 = idx & 31u;

    float4 v = ((const float4*)x)[idx];
    const float4 g = ((const float4*)g_gate)[b * 32 + c4];
    v.x *= g.x; v.y *= g.y; v.z *= g.z; v.w *= g.w;
    ((float4*)out)[idx] = v;
}

// ---------------------------------------------------------------------------
extern "C" void kernel_launch(void* const* d_in, const int* in_sizes, int n_in,
                              void* d_out, int out_size) {
    const float* x  = (const float*)d_in[0];
    const float* w1 = (const float*)d_in[1];
    const float* b1 = (const float*)d_in[2];
    const float* w2 = (const float*)d_in[3];
    const float* b2 = (const float*)d_in[4];
    float* out = (float*)d_out;

    pool_kernel<<<BB * CHUNKS, 256>>>(x);
    excite_kernel<<<BB, 256>>>(w1, b1, w2, b2);
    scale_kernel<<<(N4_TOTAL + 255) / 256, 256>>>(x, out);
}

// round 2
// speedup vs baseline: 2.1086x; 2.1086x over previous
#include <cuda_runtime.h>
#include <math.h>

// Problem constants
#define BB 32
#define HW 12544          // 112*112
#define CC 128
#define RR 2048
#define CHUNKS 56
#define POS_PER_BLOCK (HW / CHUNKS)   // 224
#define N4_TOTAL (BB * HW * (CC/4))   // 12,845,056 float4s

// Scratch (device globals: no allocation allowed)
__device__ float g_partial[BB * CHUNKS * CC];
__device__ float g_h[BB * RR];
__device__ float g_gate[BB * CC];

// ---------------------------------------------------------------------------
// Kernel 1: partial global-average-pool. Each block sums POS_PER_BLOCK spatial
// positions for one (batch, chunk) over all 128 channels. Fully coalesced
// float4 reads; smem reduce; one float4 store per channel-quad.
// ---------------------------------------------------------------------------
__global__ void __launch_bounds__(256) pool_kernel(const float* __restrict__ x) {
    const int blk   = blockIdx.x;           // 0 .. B*CHUNKS-1
    const int b     = blk / CHUNKS;
    const int chunk = blk % CHUNKS;
    const int t     = threadIdx.x;          // 256
    const int lane  = t & 31;               // channel quad (c/4)
    const int grp   = t >> 5;               // 0..7 position offset

    const float4* xb = (const float4*)x
        + (size_t)b * HW * (CC/4)
        + (size_t)chunk * POS_PER_BLOCK * (CC/4);

    float4 acc = make_float4(0.f, 0.f, 0.f, 0.f);
    #pragma unroll 7
    for (int p = grp; p < POS_PER_BLOCK; p += 8) {
        float4 v = xb[(size_t)p * (CC/4) + lane];
        acc.x += v.x; acc.y += v.y; acc.z += v.z; acc.w += v.w;
    }

    __shared__ float4 sm[256];
    sm[t] = acc;
    __syncthreads();

    if (t < 32) {
        float4 s = sm[t];
        #pragma unroll
        for (int j = 1; j < 8; j++) {
            float4 v = sm[t + 32 * j];
            s.x += v.x; s.y += v.y; s.z += v.z; s.w += v.w;
        }
        ((float4*)g_partial)[(size_t)blk * 32 + t] = s;
    }
}

// ---------------------------------------------------------------------------
// Kernel 2: fc1.  grid = (R/128, B) = (16, 32) = 512 blocks, 128 threads.
// Each block: reduce the 56 partials for its batch -> mean s[128] (L2 hits),
// then each thread computes one r:  h[b][r] = gelu_tanh(s . w1[:,r] + b1[r]).
// w1 reads are coalesced (consecutive threads -> consecutive r).
// ---------------------------------------------------------------------------
__global__ void __launch_bounds__(128) fc1_kernel(
    const float* __restrict__ w1, const float* __restrict__ b1)
{
    const int rt = blockIdx.x;   // 0..15 r-tile
    const int b  = blockIdx.y;   // batch
    const int t  = threadIdx.x;  // 0..127

    __shared__ float s[CC];

    // mean over spatial: reduce the 56 partial sums for channel t
    {
        float sum = 0.f;
        const float* p = g_partial + (size_t)b * CHUNKS * CC + t;
        #pragma unroll 14
        for (int k = 0; k < CHUNKS; k++) sum += p[(size_t)k * CC];
        s[t] = sum * (1.0f / (float)HW);
    }
    __syncthreads();

    const int r = rt * 128 + t;
    float acc = b1[r];
    #pragma unroll
    for (int c = 0; c < CC; c++)
        acc = fmaf(s[c], w1[(size_t)c * RR + r], acc);

    // tanh-approx GELU (jax.nn.gelu default)
    const float u = acc;
    const float inner = 0.7978845608028654f * (u + 0.044715f * u * u * u);
    g_h[(size_t)b * RR + r] = 0.5f * u * (1.0f + tanhf(inner));
}

// ---------------------------------------------------------------------------
// Kernel 3: fc2.  grid = B = 32 blocks, 1024 threads.
// Thread (c = t&127, chunk = t>>7) accumulates 256 r of h[b][r]*w2[r][c]
// (w2 reads coalesced across c; h reads are warp-broadcast), then an 8-way
// smem reduce + sigmoid -> g_gate[b][c].
// ---------------------------------------------------------------------------
__global__ void __launch_bounds__(1024) fc2_kernel(
    const float* __restrict__ w2, const float* __restrict__ b2)
{
    const int b     = blockIdx.x;
    const int t     = threadIdx.x;
    const int c     = t & 127;
    const int chunk = t >> 7;            // 0..7, 256 r each

    const float* hp  = g_h + (size_t)b * RR + chunk * 256;
    const float* w2p = w2 + (size_t)chunk * 256 * CC + c;

    float acc = 0.f;
    #pragma unroll 8
    for (int r = 0; r < 256; r++)
        acc = fmaf(hp[r], w2p[(size_t)r * CC], acc);

    __shared__ float red[1024];
    red[t] = acc;
    __syncthreads();

    if (t < CC) {
        float v = b2[t];
        #pragma unroll
        for (int j = 0; j < 8; j++) v += red[t + 128 * j];
        g_gate[b * CC + t] = 1.0f / (1.0f + expf(-v));
    }
}

// ---------------------------------------------------------------------------
// Kernel 4: out = x * gate[b, c]  (float4 vectorized, gate hits L1/L2)
// ---------------------------------------------------------------------------
__global__ void __launch_bounds__(256) scale_kernel(const float* __restrict__ x,
                                                    float* __restrict__ out) {
    const unsigned idx = blockIdx.x * 256u + threadIdx.x;   // float4 index
    if (idx >= (unsigned)N4_TOTAL) return;
    const unsigned b  = idx / (HW * (CC / 4));   // / 401408
    const unsigned c4 = idx & 31u;

    float4 v = ((const float4*)x)[idx];
    const float4 g = ((const float4*)g_gate)[b * 32 + c4];
    v.x *= g.x; v.y *= g.y; v.z *= g.z; v.w *= g.w;
    ((float4*)out)[idx] = v;
}

// ---------------------------------------------------------------------------
extern "C" void kernel_launch(void* const* d_in, const int* in_sizes, int n_in,
                              void* d_out, int out_size) {
    const float* x  = (const float*)d_in[0];
    const float* w1 = (const float*)d_in[1];
    const float* b1 = (const float*)d_in[2];
    const float* w2 = (const float*)d_in[3];
    const float* b2 = (const float*)d_in[4];
    float* out = (float*)d_out;

    pool_kernel<<<BB * CHUNKS, 256>>>(x);
    fc1_kernel<<<dim3(RR / 128, BB), 128>>>(w1, b1);
    fc2_kernel<<<BB, 1024>>>(w2, b2);
    scale_kernel<<<(N4_TOTAL + 255) / 256, 256>>>(x, out);
}